// round 4
// baseline (speedup 1.0000x reference)
#include <cuda_runtime.h>
#include <math.h>

#define NN 10000
#define EE 160000
#define FF 32
#define NCH 9

// ---------------- device scratch (static, no allocations) ----------------
__device__ float g_x[NN * NCH * FF];     // node features
__device__ float g_y[NN * NCH * FF];     // message accumulator (x + segsum target)
__device__ float g_geo[EE * 25];         // per edge: sph[9], rad[16] (rad includes cutoff fc)

struct CGc { float v[729]; };

// ---------------- host: analytic Gaunt coefficients -----------------------
// Integral over unit sphere of x^p y^q z^r: 0 if any odd, else
// 4*pi * (p-1)!!(q-1)!!(r-1)!! / (p+q+r+1)!!
static double dfact_h(int n) { double v = 1.0; for (int k = n; k >= 2; k -= 2) v *= (double)k; return v; }

static void compute_cg(CGc* cg) {
    const double c0 = 0.28209479177387814, c1 = 0.4886025119029199,
                 c2a = 1.0925484305920792, c2b = 0.31539156525252005,
                 c2c = 0.5462742152960396;
    double tc[9][2]; int te[9][2][3]; int nt[9];
    for (int i = 0; i < 9; i++) { nt[i] = 1; tc[i][1] = 0.0; te[i][1][0] = te[i][1][1] = te[i][1][2] = 0; }
    // Y0..Y8 as monomial terms
    tc[0][0] = c0;      te[0][0][0]=0; te[0][0][1]=0; te[0][0][2]=0;
    tc[1][0] = c1;      te[1][0][0]=0; te[1][0][1]=1; te[1][0][2]=0;
    tc[2][0] = c1;      te[2][0][0]=0; te[2][0][1]=0; te[2][0][2]=1;
    tc[3][0] = c1;      te[3][0][0]=1; te[3][0][1]=0; te[3][0][2]=0;
    tc[4][0] = c2a;     te[4][0][0]=1; te[4][0][1]=1; te[4][0][2]=0;
    tc[5][0] = c2a;     te[5][0][0]=0; te[5][0][1]=1; te[5][0][2]=1;
    tc[6][0] = 3.0*c2b; te[6][0][0]=0; te[6][0][1]=0; te[6][0][2]=2;
    tc[6][1] = -c2b;    te[6][1][0]=0; te[6][1][1]=0; te[6][1][2]=0; nt[6] = 2;
    tc[7][0] = c2a;     te[7][0][0]=1; te[7][0][1]=0; te[7][0][2]=1;
    tc[8][0] = c2c;     te[8][0][0]=2; te[8][0][1]=0; te[8][0][2]=0;
    tc[8][1] = -c2c;    te[8][1][0]=0; te[8][1][1]=2; te[8][1][2]=0; nt[8] = 2;

    const double fourpi = 12.566370614359172464;
    for (int a = 0; a < 9; a++)
      for (int b = 0; b < 9; b++)
        for (int c = 0; c < 9; c++) {
            double g = 0.0;
            for (int i = 0; i < nt[a]; i++)
              for (int j = 0; j < nt[b]; j++)
                for (int k = 0; k < nt[c]; k++) {
                    int p = te[a][i][0] + te[b][j][0] + te[c][k][0];
                    int q = te[a][i][1] + te[b][j][1] + te[c][k][1];
                    int r = te[a][i][2] + te[b][j][2] + te[c][k][2];
                    if ((p | q | r) & 1) continue;
                    double I = fourpi * dfact_h(p - 1) * dfact_h(q - 1) * dfact_h(r - 1)
                               / dfact_h(p + q + r + 1);
                    g += tc[a][i] * tc[b][j] * tc[c][k] * I;
                }
            if (fabs(g) < 1e-6) g = 0.0;   // match reference thresholding
            cg->v[(a * 9 + b) * 9 + c] = (float)g;
        }
}

// ---------------- kernels -------------------------------------------------

// x[:,0,:] = embed[z]; rest 0. Also zero y for iteration 0.
__global__ void k_init(const int* __restrict__ z, const float* __restrict__ embed) {
    int idx = blockIdx.x * blockDim.x + threadIdx.x;
    if (idx >= NN * NCH * FF) return;
    g_y[idx] = 0.0f;
    int f = idx & 31;
    int c = (idx >> 5) % 9;
    int n = idx / (NCH * FF);
    g_x[idx] = (c == 0) ? embed[z[n] * FF + f] : 0.0f;
}

// per-edge geometry: sph9(u) and radial(r)*fc -> 25 floats
__global__ void k_geom(const float* __restrict__ pos, const int* __restrict__ dst,
                       const int* __restrict__ src) {
    int e = blockIdx.x * blockDim.x + threadIdx.x;
    if (e >= EE) return;
    int s = src[e], d = dst[e];
    float dx = pos[s * 3 + 0] - pos[d * 3 + 0];
    float dy = pos[s * 3 + 1] - pos[d * 3 + 1];
    float dz = pos[s * 3 + 2] - pos[d * 3 + 2];
    float r = sqrtf(dx * dx + dy * dy + dz * dz + 1e-12f);
    float inv = 1.0f / r;
    float x = dx * inv, y = dy * inv, z = dz * inv;
    const float c0 = 0.28209479177387814f, c1 = 0.4886025119029199f,
                c2a = 1.0925484305920792f, c2b = 0.31539156525252005f,
                c2c = 0.5462742152960396f;
    float* g = &g_geo[(size_t)e * 25];
    g[0] = c0;
    g[1] = c1 * y;  g[2] = c1 * z;  g[3] = c1 * x;
    g[4] = c2a * x * y; g[5] = c2a * y * z;
    g[6] = c2b * (3.0f * z * z - 1.0f);
    g[7] = c2a * x * z; g[8] = c2c * (x * x - y * y);

    float u1 = 1.0f / (1.0f + r);
    float om = 1.0f - u1;
    float A[16], B[16];
    A[0] = 1.0f;
    #pragma unroll
    for (int k = 1; k < 16; k++) A[k] = A[k - 1] * u1;
    B[15] = 1.0f;
    #pragma unroll
    for (int k = 14; k >= 0; k--) B[k] = B[k + 1] * om;
    float t = r * 0.25f;
    float fc = 0.0f;
    if (t < 1.0f) {
        float den = 1.0f - t * t;
        fc = expf(-t * t / den);
    }
    const float binom[16] = {1.f,15.f,105.f,455.f,1365.f,3003.f,5005.f,6435.f,
                             6435.f,5005.f,3003.f,1365.f,455.f,105.f,15.f,1.f};
    #pragma unroll
    for (int k = 0; k < 16; k++) g[9 + k] = binom[k] * A[k] * B[k] * fc;
}

// edge kernel: msg[e,c,f] = sum_{a,b} CG[a,b,c] * x_src[a,f] * sph[b] * R[deg(b),f]
// atomically accumulated into g_y[dst].
__global__ void __launch_bounds__(256, 2)
k_edge(const int* __restrict__ dst, const int* __restrict__ src,
       const float* __restrict__ Wb_i, CGc cg) {
    const int lane = threadIdx.x & 31;
    const int warp = (blockIdx.x * blockDim.x + threadIdx.x) >> 5;
    const int nwarp = (gridDim.x * blockDim.x) >> 5;

    // preload this iteration's radial weights: w[d][n] for my feature lane
    float w0[16], w1[16], w2[16];
    #pragma unroll
    for (int n = 0; n < 16; n++) {
        w0[n] = Wb_i[(0 * 16 + n) * 32 + lane];
        w1[n] = Wb_i[(1 * 16 + n) * 32 + lane];
        w2[n] = Wb_i[(2 * 16 + n) * 32 + lane];
    }

    for (int e = warp; e < EE; e += nwarp) {
        int s = src[e], d = dst[e];
        float gv = g_geo[(size_t)e * 25 + (lane < 25 ? lane : 0)];

        float R0 = 0.f, R1 = 0.f, R2 = 0.f;
        #pragma unroll
        for (int n = 0; n < 16; n++) {
            float rn = __shfl_sync(0xffffffffu, gv, 9 + n);
            R0 = fmaf(rn, w0[n], R0);
            R1 = fmaf(rn, w1[n], R1);
            R2 = fmaf(rn, w2[n], R2);
        }
        float bfv[9];
        #pragma unroll
        for (int b = 0; b < 9; b++) {
            float sb = __shfl_sync(0xffffffffu, gv, b);
            bfv[b] = sb * (b == 0 ? R0 : (b < 4 ? R1 : R2));
        }
        float xa[9];
        const float* xp = &g_x[(size_t)s * 288 + lane];
        #pragma unroll
        for (int a = 0; a < 9; a++) xa[a] = xp[a * 32];

        float msg[9];
        #pragma unroll
        for (int c = 0; c < 9; c++) msg[c] = 0.f;

#define GV(A,B,C) cg.v[(A)*81 + (B)*9 + (C)]
#define TPA(A,B,C) msg[C] = fmaf(GV(A,B,C), xa[A] * bfv[B], msg[C]);
#define TPS(A,B,C) msg[C] = fmaf(GV(A,B,C), fmaf(xa[A], bfv[B], xa[B] * bfv[A]), msg[C]);
        // c = 0 (scalar)
        TPA(0,0,0) TPA(1,1,0) TPA(2,2,0) TPA(3,3,0) TPA(4,4,0)
        TPA(5,5,0) TPA(6,6,0) TPA(7,7,0) TPA(8,8,0)
        TPS(0,6,0) TPS(0,8,0) TPS(6,8,0)
        // c = 6 (3z^2-1)
        TPA(0,0,6) TPA(1,1,6) TPA(2,2,6) TPA(3,3,6) TPA(4,4,6)
        TPA(5,5,6) TPA(6,6,6) TPA(7,7,6) TPA(8,8,6)
        TPS(0,6,6) TPS(0,8,6) TPS(6,8,6)
        // c = 8 (x^2-y^2)
        TPA(0,0,8) TPA(1,1,8) TPA(2,2,8) TPA(3,3,8) TPA(4,4,8)
        TPA(5,5,8) TPA(6,6,8) TPA(7,7,8) TPA(8,8,8)
        TPS(0,6,8) TPS(0,8,8) TPS(6,8,8)
        // c = 1 (y)
        TPS(0,1,1) TPS(6,1,1) TPS(8,1,1) TPS(3,4,1) TPS(2,5,1)
        // c = 2 (z)
        TPS(0,2,2) TPS(6,2,2) TPS(8,2,2) TPS(3,7,2) TPS(1,5,2)
        // c = 3 (x)
        TPS(0,3,3) TPS(6,3,3) TPS(8,3,3) TPS(1,4,3) TPS(2,7,3)
        // c = 4 (xy)
        TPS(0,4,4) TPS(6,4,4) TPS(8,4,4) TPS(1,3,4) TPS(5,7,4)
        // c = 5 (yz)
        TPS(0,5,5) TPS(6,5,5) TPS(8,5,5) TPS(1,2,5) TPS(4,7,5)
        // c = 7 (xz)
        TPS(0,7,7) TPS(6,7,7) TPS(8,7,7) TPS(2,3,7) TPS(4,5,7)
#undef GV
#undef TPA
#undef TPS

        float* yp = &g_y[(size_t)d * 288 + lane];
        #pragma unroll
        for (int c = 0; c < 9; c++) atomicAdd(&yp[c * 32], msg[c]);
    }
}

// node kernel: y = x + agg; y = silu(W1 y + b1); y = W2 y + b2; x += y
// Also re-zeroes g_y for the next iteration.
__global__ void __launch_bounds__(256)
k_node(const float* __restrict__ W1, const float* __restrict__ b1,
       const float* __restrict__ W2, const float* __restrict__ b2) {
    __shared__ float sW1[3 * 32 * 32], sW2[3 * 32 * 32], sb1[32], sb2[32];
    int t = threadIdx.x;
    for (int i = t; i < 3072; i += 256) { sW1[i] = W1[i]; sW2[i] = W2[i]; }
    if (t < 32) { sb1[t] = b1[t]; sb2[t] = b2[t]; }
    __syncthreads();

    int lane = t & 31;
    int n = (blockIdx.x * 256 + t) >> 5;
    if (n >= NN) return;

    const int DEGc[9] = {0, 1, 1, 1, 2, 2, 2, 2, 2};
    float yv[9], h[9];
    #pragma unroll
    for (int c = 0; c < 9; c++) {
        int idx = n * 288 + c * 32 + lane;
        yv[c] = g_x[idx] + g_y[idx];
        g_y[idx] = 0.0f;
    }
    #pragma unroll
    for (int c = 0; c < 9; c++) {
        int d = DEGc[c];
        float acc = (c == 0) ? sb1[lane] : 0.0f;
        #pragma unroll
        for (int f = 0; f < 32; f++) {
            float v = __shfl_sync(0xffffffffu, yv[c], f);
            acc = fmaf(v, sW1[(d * 32 + f) * 32 + lane], acc);
        }
        h[c] = acc / (1.0f + expf(-acc));   // silu
    }
    #pragma unroll
    for (int c = 0; c < 9; c++) {
        int d = DEGc[c];
        float acc = (c == 0) ? sb2[lane] : 0.0f;
        #pragma unroll
        for (int f = 0; f < 32; f++) {
            float v = __shfl_sync(0xffffffffu, h[c], f);
            acc = fmaf(v, sW2[(d * 32 + f) * 32 + lane], acc);
        }
        g_x[n * 288 + c * 32 + lane] += acc;
    }
}

// output head: mono (N,4) then dip (N,3,4)
__global__ void __launch_bounds__(256)
k_out(const int* __restrict__ z, const float* __restrict__ pos,
      const float* __restrict__ Wt00, const float* __restrict__ Wt11,
      const float* __restrict__ Wmono, const float* __restrict__ ebias,
      float* __restrict__ out) {
    int lane = threadIdx.x & 31;
    int n = (blockIdx.x * blockDim.x + threadIdx.x) >> 5;
    if (n >= NN) return;

    float x0 = g_x[n * 288 + lane];
    float tj[4];
    #pragma unroll
    for (int j = 0; j < 4; j++) {
        float p = x0 * Wt00[lane * 4 + j];
        #pragma unroll
        for (int o = 16; o > 0; o >>= 1) p += __shfl_xor_sync(0xffffffffu, p, o);
        tj[j] = p;
    }
    if (lane < 4) {
        float m = 0.0f;
        #pragma unroll
        for (int k = 0; k < 4; k++) m = fmaf(tj[k], Wmono[k * 4 + lane], m);
        m += ebias[z[n]];
        out[n * 4 + lane] = m;
    }
    #pragma unroll
    for (int c = 0; c < 3; c++) {
        float xc = g_x[n * 288 + (1 + c) * 32 + lane];
        #pragma unroll
        for (int j = 0; j < 4; j++) {
            float p = xc * Wt11[lane * 4 + j];
            #pragma unroll
            for (int o = 16; o > 0; o >>= 1) p += __shfl_xor_sync(0xffffffffu, p, o);
            if (lane == 0) {
                float sv = p / (1.0f + expf(-p));
                sv = fminf(fmaxf(sv, -0.3f), 0.3f);
                out[NN * 4 + (n * 3 + c) * 4 + j] = sv + pos[n * 3 + c];
            }
        }
    }
}

// ---------------- launch --------------------------------------------------
extern "C" void kernel_launch(void* const* d_in, const int* in_sizes, int n_in,
                              void* d_out, int out_size) {
    const int*   z     = (const int*)d_in[0];
    const float* pos   = (const float*)d_in[1];
    const int*   dst   = (const int*)d_in[2];
    const int*   src   = (const int*)d_in[3];
    const float* embed = (const float*)d_in[4];
    const float* Wb    = (const float*)d_in[5];
    const float* W1    = (const float*)d_in[6];
    const float* b1    = (const float*)d_in[7];
    const float* W2    = (const float*)d_in[8];
    const float* b2    = (const float*)d_in[9];
    const float* Wt00  = (const float*)d_in[10];
    const float* Wt11  = (const float*)d_in[11];
    const float* Wmono = (const float*)d_in[12];
    const float* ebias = (const float*)d_in[13];
    float* out = (float*)d_out;

    CGc cg;
    compute_cg(&cg);   // deterministic pure-host constant, recomputed every call

    k_init<<<(NN * NCH * FF + 255) / 256, 256>>>(z, embed);
    k_geom<<<(EE + 255) / 256, 256>>>(pos, dst, src);
    for (int i = 0; i < 3; i++) {
        k_edge<<<2048, 256>>>(dst, src, Wb + i * 3 * 16 * 32, cg);
        k_node<<<(NN * 32 + 255) / 256, 256>>>(W1 + i * 3 * 32 * 32, b1 + i * 32,
                                               W2 + i * 3 * 32 * 32, b2 + i * 32);
    }
    k_out<<<(NN * 32 + 255) / 256, 256>>>(z, pos, Wt00, Wt11, Wmono, ebias, out);
}